// round 2
// baseline (speedup 1.0000x reference)
#include <cuda_runtime.h>

#define BB 1024
#define SS 512
#define DD 128
#define HH 128
#define G4 512    // 4*H
#define KTOT 256  // D + H
#define NOPS 16
#define BC 8           // samples per CTA
#define NCTA (BB/BC)   // 128
#define NTHR 512
#define NC 88          // weight k-rows cached in smem

// Transposed combined weights: g_Wt[k*512 + g] = W_ih[g][k] (k<128) else W_hh[g][k-128]
__device__ float g_Wt[KTOT * G4];
__device__ float g_bias[G4];

typedef unsigned long long u64;

__device__ __forceinline__ u64 pack2(float x) {
    u64 r; asm("mov.b64 %0,{%1,%1};" : "=l"(r) : "f"(x)); return r;
}
__device__ __forceinline__ u64 fma2(u64 a, u64 b, u64 c) {
    u64 d; asm("fma.rn.f32x2 %0,%1,%2,%3;" : "=l"(d) : "l"(a), "l"(b), "l"(c)); return d;
}
__device__ __forceinline__ void unpack2(u64 v, float& lo, float& hi) {
    asm("mov.b64 {%0,%1},%2;" : "=f"(lo), "=f"(hi) : "l"(v));
}

__global__ void setup_kernel(const float* __restrict__ Wih, const float* __restrict__ Whh,
                             const float* __restrict__ bih, const float* __restrict__ bhh) {
    int idx = blockIdx.x * blockDim.x + threadIdx.x;
    if (idx < KTOT * G4) {
        int k = idx >> 9;
        int g = idx & (G4 - 1);
        g_Wt[idx] = (k < DD) ? Wih[g * DD + k] : Whh[g * HH + (k - DD)];
    }
    if (idx < G4) g_bias[idx] = bih[idx] + bhh[idx];
}

extern "C" __global__ void __launch_bounds__(NTHR, 1)
lstm_kernel(const int* __restrict__ tokens, const int* __restrict__ lengths,
            const float* __restrict__ onehot, const float* __restrict__ emb,
            const float* __restrict__ h0, const float* __restrict__ c0,
            const float* __restrict__ linW, const float* __restrict__ linb,
            float* __restrict__ out) {
    extern __shared__ float sW[];  // NC * 512 floats

    __shared__ __align__(16) float xh[KTOT * BC];  // [k][sample] : x (k<128) then h
    __shared__ float gact[G4 * 9];                 // activated gates, padded stride 9
    __shared__ float cs[HH * 9];                   // cell state, padded
    __shared__ float hl[HH * 9];                   // last-hidden snapshot (relu'd)
    __shared__ int len_s[BC];

    const int tid = threadIdx.x;
    const int base_s = blockIdx.x * BC;

    // cache first NC weight rows into smem
    for (int i = tid; i < NC * G4; i += NTHR) sW[i] = g_Wt[i];

    // init h, c
    if (tid < HH) {
        float h0v = h0[tid], c0v = c0[tid];
#pragma unroll
        for (int s = 0; s < BC; s++) {
            xh[(DD + tid) * BC + s] = h0v;
            cs[tid * 9 + s] = c0v;
        }
    }
    if (tid < BC) len_s[tid] = lengths[base_s + tid];

    const int g = tid;
    const float bias = g_bias[g];
    const bool is_tanh_gate = ((g >> 7) == 2);  // gate order: i, f, g, o
    const int j = tid & (HH - 1);
    const int supd = (tid >> 7) * 2;

    const int gath_s = tid >> 6;           // phase-0 sample
    const int gath_k = (tid & 63) * 2;     // phase-0 dim pair

    __syncthreads();

    for (int t = 0; t < SS; t++) {
        // ---- phase 0: x_t = relu(embedding[token]) ----
        {
            int tok = tokens[(base_s + gath_s) * SS + t];
            float2 e = *(const float2*)(emb + tok * DD + gath_k);
            xh[gath_k * BC + gath_s] = fmaxf(e.x, 0.f);
            xh[(gath_k + 1) * BC + gath_s] = fmaxf(e.y, 0.f);
        }
        __syncthreads();

        // ---- phase 1: gates[g][s] = bias + sum_k W[g][k] * xh[k][s] ----
        u64 a0 = pack2(bias), a1 = a0, a2 = a0, a3 = a0;
#pragma unroll 4
        for (int k = 0; k < NC; k++) {
            u64 wp = pack2(sW[k * G4 + g]);
            ulonglong2 va = *(const ulonglong2*)(xh + k * BC);
            ulonglong2 vb = *(const ulonglong2*)(xh + k * BC + 4);
            a0 = fma2(wp, va.x, a0);
            a1 = fma2(wp, va.y, a1);
            a2 = fma2(wp, vb.x, a2);
            a3 = fma2(wp, vb.y, a3);
        }
#pragma unroll 4
        for (int k = NC; k < KTOT; k++) {
            u64 wp = pack2(g_Wt[k * G4 + g]);
            ulonglong2 va = *(const ulonglong2*)(xh + k * BC);
            ulonglong2 vb = *(const ulonglong2*)(xh + k * BC + 4);
            a0 = fma2(wp, va.x, a0);
            a1 = fma2(wp, va.y, a1);
            a2 = fma2(wp, vb.x, a2);
            a3 = fma2(wp, vb.y, a3);
        }

        // activation + store to gact
        {
            float v[8];
            unpack2(a0, v[0], v[1]);
            unpack2(a1, v[2], v[3]);
            unpack2(a2, v[4], v[5]);
            unpack2(a3, v[6], v[7]);
#pragma unroll
            for (int s = 0; s < 8; s++) {
                float a = v[s];
                float r = is_tanh_gate ? tanhf(a) : (1.f / (1.f + __expf(-a)));
                gact[g * 9 + s] = r;
            }
        }
        __syncthreads();

        // ---- phase 2: c, h update (thread -> (j, 2 samples)) ----
#pragma unroll
        for (int ds = 0; ds < 2; ds++) {
            int s = supd + ds;
            float iv = gact[j * 9 + s];
            float fv = gact[(HH + j) * 9 + s];
            float gv = gact[(2 * HH + j) * 9 + s];
            float ov = gact[(3 * HH + j) * 9 + s];
            float c = cs[j * 9 + s];
            float cn = fmaf(fv, c, iv * gv);
            float hh = ov * tanhf(cn);
            cs[j * 9 + s] = cn;
            xh[(DD + j) * BC + s] = hh;
            if (t == len_s[s] - 1) hl[j * 9 + s] = fmaxf(hh, 0.f);
        }
        __syncthreads();
    }

    // ---- output: logits = [relu(h_last), onehot] @ linW^T + linb ----
    if (tid < BC * 2) {
        int s = tid >> 1, m = tid & 1;
        float acc = linb[m];
#pragma unroll 4
        for (int jj = 0; jj < HH; jj++)
            acc = fmaf(hl[jj * 9 + s], linW[m * (HH + NOPS) + jj], acc);
#pragma unroll
        for (int p = 0; p < NOPS; p++)
            acc = fmaf(onehot[(base_s + s) * NOPS + p], linW[m * (HH + NOPS) + DD + p], acc);
        out[(base_s + s) * 2 + m] = acc;
    }
}

extern "C" void kernel_launch(void* const* d_in, const int* in_sizes, int n_in,
                              void* d_out, int out_size) {
    const int* tokens = (const int*)d_in[0];
    const int* lengths = (const int*)d_in[1];
    const float* onehot = (const float*)d_in[2];
    const float* emb = (const float*)d_in[3];
    const float* Wih = (const float*)d_in[4];
    const float* Whh = (const float*)d_in[5];
    const float* bih = (const float*)d_in[6];
    const float* bhh = (const float*)d_in[7];
    const float* h0 = (const float*)d_in[8];
    const float* c0 = (const float*)d_in[9];
    const float* linW = (const float*)d_in[10];
    const float* linb = (const float*)d_in[11];
    float* out = (float*)d_out;

    setup_kernel<<<(KTOT * G4 + 255) / 256, 256>>>(Wih, Whh, bih, bhh);

    size_t dyn = (size_t)NC * G4 * sizeof(float);
    cudaFuncSetAttribute(lstm_kernel, cudaFuncAttributeMaxDynamicSharedMemorySize, (int)dyn);
    lstm_kernel<<<NCTA, NTHR, dyn>>>(tokens, lengths, onehot, emb, h0, c0, linW, linb, out);
}